// round 3
// baseline (speedup 1.0000x reference)
#include <cuda_runtime.h>
#include <cstdint>

// ---------------- problem constants ----------------
#define BATCH   32
#define NTOK    1024
#define DDIM    1024
#define MFF     4096
#define LN_EPS  1e-5f
#define GKC     32

#define MS_SPLIT 16
#define F1_SPLIT 8
#define F2_SPLIT 32

// ---------------- scratch ----------------
__device__ float g_x    [BATCH * NTOK];
__device__ float g_qstat[64];                 // (mean, rstd) per Q row
__device__ float g_xraw [64];                 // (sum, sumsq) per x row (atomics)
__device__ float g_part [2097152];            // split-K partials (8 MB)

#define MU_OFF  0                             // 16*32*1024 = 524288
#define SIG_OFF 524288
#define W1_OFF  0                             // 8*32*4096 = 1048576 (reuse)
#define W2_OFF  1048576                       // 32*32*1024 = 1048576

// =====================================================================
// Q row stats (mean, rstd) + zero the x-stat accumulators. 1 block.
// =====================================================================
__global__ void stats_kernel(const float* __restrict__ Q)
{
    const int tid = threadIdx.x;
    if (tid < 64) g_xraw[tid] = 0.f;
    const int r = tid >> 5, lane = tid & 31;
    const float4* p = reinterpret_cast<const float4*>(Q + r * NTOK);
    float s = 0.f, ss = 0.f;
    #pragma unroll
    for (int i = 0; i < 8; ++i) {
        float4 v = p[lane + 32 * i];
        s  += v.x + v.y + v.z + v.w;
        ss += v.x*v.x + v.y*v.y + v.z*v.z + v.w*v.w;
    }
    #pragma unroll
    for (int o = 16; o; o >>= 1) {
        s  += __shfl_xor_sync(0xffffffffu, s,  o);
        ss += __shfl_xor_sync(0xffffffffu, ss, o);
    }
    if (lane == 0) {
        const float mean = s * (1.0f / NTOK);
        const float var  = ss * (1.0f / NTOK) - mean * mean;
        g_qstat[2 * r]     = mean;
        g_qstat[2 * r + 1] = rsqrtf(var + LN_EPS);
    }
}

// =====================================================================
// Split-K GEMM, block tile 32(M) x 128(N), K-chunk 32, double-buffered.
// AMODE 0: A = LN(Q) via precomputed g_qstat
// AMODE 1: A = LN(g_x) via g_xraw (finalized per thread)
// AMODE 2: A = silu(sum of F1_SPLIT partials + b1)
// A duplicated in smem ({v,v} pairs) so inner loop is
//   2 LDS.128 (W, 8n) + 2 LDS.64 (A-dup, 2m) + 8 fma.f32x2.
// gridDim = (N/128, nsplit, nz); z selects W0/W1 (mu/sigma).
// =====================================================================
template<int AMODE>
__global__ __launch_bounds__(256, 2)
void gemm_kernel(const float* __restrict__ W0, const float* __restrict__ W1,
                 int ldw, int N, int kPerSplit, int partOff, int partStrideZ,
                 const float* __restrict__ Ain,
                 const float* __restrict__ lng, const float* __restrict__ lnb,
                 const float* __restrict__ b1)
{
    __shared__ __align__(16) float a_s[2][GKC][66];
    __shared__ __align__(16) float w_s[2][GKC][132];

    const int tid = threadIdx.x;
    const float* __restrict__ W = (blockIdx.z == 0) ? W0 : W1;
    float* __restrict__ P = g_part + partOff + (size_t)blockIdx.z * partStrideZ;

    const int j0    = blockIdx.x * 128;
    const int split = blockIdx.y;
    const int kOff  = split * kPerSplit;
    const int T     = kPerSplit / GKC;

    // loader mappings
    const int ra = tid >> 3, ca = tid & 7, c4 = ca * 4;       // A: 32m x 8 k-groups
    const int wr = tid & 127, wkb = (tid >> 7) * 16;          // W: 128n x 2 k-halves
    // compute mapping
    const int tx = tid & 15, ty = tid >> 4;                   // n-octet, m

    float mean = 0.f, rs = 0.f;
    if (AMODE == 0) { mean = g_qstat[2 * ra]; rs = g_qstat[2 * ra + 1]; }
    if (AMODE == 1) {
        const float s  = g_xraw[2 * ra];
        const float ss = g_xraw[2 * ra + 1];
        mean = s * (1.0f / NTOK);
        rs   = rsqrtf(ss * (1.0f / NTOK) - mean * mean + LN_EPS);
    }

    const float* Wrow = W + (size_t)(j0 + wr) * ldw + kOff + wkb;
    const float* Arow = (AMODE == 1) ? (g_x + ra * NTOK) : (Ain + ra * NTOK);

    float fwv[16];
    float av[4];

    auto loadG = [&](int t) {
        const int kb = t * GKC;
        #pragma unroll
        for (int j = 0; j < 4; ++j) {
            float4 f = *reinterpret_cast<const float4*>(Wrow + kb + 4 * j);
            fwv[4*j+0] = f.x; fwv[4*j+1] = f.y; fwv[4*j+2] = f.z; fwv[4*j+3] = f.w;
        }
        const int kc = kOff + kb + c4;
        if (AMODE < 2) {
            const float4 fa = *reinterpret_cast<const float4*>(Arow + kc);
            const float4 fg = *reinterpret_cast<const float4*>(lng + kc);
            const float4 fb = *reinterpret_cast<const float4*>(lnb + kc);
            av[0] = (fa.x - mean) * rs * fg.x + fb.x;
            av[1] = (fa.y - mean) * rs * fg.y + fb.y;
            av[2] = (fa.z - mean) * rs * fg.z + fb.z;
            av[3] = (fa.w - mean) * rs * fg.w + fb.w;
        } else {
            float4 v = *reinterpret_cast<const float4*>(b1 + kc);
            #pragma unroll
            for (int s = 0; s < F1_SPLIT; ++s) {
                const float4 p = *reinterpret_cast<const float4*>(
                    g_part + W1_OFF + (size_t)(s * BATCH + ra) * MFF + kc);
                v.x += p.x; v.y += p.y; v.z += p.z; v.w += p.w;
            }
            av[0] = v.x / (1.0f + __expf(-v.x));
            av[1] = v.y / (1.0f + __expf(-v.y));
            av[2] = v.z / (1.0f + __expf(-v.z));
            av[3] = v.w / (1.0f + __expf(-v.w));
        }
    };

    auto storeS = [&](int buf) {
        #pragma unroll
        for (int j = 0; j < 4; ++j)
            *reinterpret_cast<float2*>(&a_s[buf][c4 + j][2 * ra]) =
                make_float2(av[j], av[j]);
        #pragma unroll
        for (int j = 0; j < 16; ++j)
            w_s[buf][wkb + j][wr] = fwv[j];
    };

    loadG(0);
    storeS(0);
    __syncthreads();

    unsigned long long acc[2][4];
    #pragma unroll
    for (int i = 0; i < 2; ++i)
        #pragma unroll
        for (int j = 0; j < 4; ++j) acc[i][j] = 0ull;

    for (int t = 0; t < T; ++t) {
        const int cur = t & 1;
        if (t + 1 < T) loadG(t + 1);
        #pragma unroll
        for (int kk = 0; kk < GKC; ++kk) {
            const ulonglong2 wv0 =
                *reinterpret_cast<const ulonglong2*>(&w_s[cur][kk][8 * tx]);
            const ulonglong2 wv1 =
                *reinterpret_cast<const ulonglong2*>(&w_s[cur][kk][8 * tx + 4]);
            const unsigned long long a0 =
                *reinterpret_cast<const unsigned long long*>(&a_s[cur][kk][2 * ty]);
            const unsigned long long a1 =
                *reinterpret_cast<const unsigned long long*>(&a_s[cur][kk][2 * ty + 32]);
            asm("fma.rn.f32x2 %0, %1, %2, %0;" : "+l"(acc[0][0]) : "l"(a0), "l"(wv0.x));
            asm("fma.rn.f32x2 %0, %1, %2, %0;" : "+l"(acc[0][1]) : "l"(a0), "l"(wv0.y));
            asm("fma.rn.f32x2 %0, %1, %2, %0;" : "+l"(acc[0][2]) : "l"(a0), "l"(wv1.x));
            asm("fma.rn.f32x2 %0, %1, %2, %0;" : "+l"(acc[0][3]) : "l"(a0), "l"(wv1.y));
            asm("fma.rn.f32x2 %0, %1, %2, %0;" : "+l"(acc[1][0]) : "l"(a1), "l"(wv0.x));
            asm("fma.rn.f32x2 %0, %1, %2, %0;" : "+l"(acc[1][1]) : "l"(a1), "l"(wv0.y));
            asm("fma.rn.f32x2 %0, %1, %2, %0;" : "+l"(acc[1][2]) : "l"(a1), "l"(wv1.x));
            asm("fma.rn.f32x2 %0, %1, %2, %0;" : "+l"(acc[1][3]) : "l"(a1), "l"(wv1.y));
        }
        if (t + 1 < T) {
            storeS((t + 1) & 1);
            __syncthreads();
        }
    }

    // epilogue: m in {ty, ty+16}, n in [j0+8tx, j0+8tx+8)
    #pragma unroll
    for (int mi = 0; mi < 2; ++mi) {
        const int m = ty + 16 * mi;
        float f[8];
        #pragma unroll
        for (int j = 0; j < 4; ++j)
            asm("mov.b64 {%0, %1}, %2;" : "=f"(f[2*j]), "=f"(f[2*j+1]) : "l"(acc[mi][j]));
        float* dst = P + (size_t)(split * BATCH + m) * N + j0 + 8 * tx;
        *reinterpret_cast<float4*>(dst)     = make_float4(f[0], f[1], f[2], f[3]);
        *reinterpret_cast<float4*>(dst + 4) = make_float4(f[4], f[5], f[6], f[7]);
    }
}

// =====================================================================
// Gaussian pseudo-attention: one warp per (b,i), streams K/V (256 MB).
// Folds mu/sigma split-K combine; accumulates LN(x) stats via atomics.
// =====================================================================
__global__ __launch_bounds__(256)
void gauss_kernel(const float* __restrict__ Kp,
                  const float* __restrict__ Vp,
                  const float* __restrict__ Qp,
                  const float* __restrict__ mu_b,
                  const float* __restrict__ sig_b)
{
    const int tid  = threadIdx.x;
    const int w    = blockIdx.x * 8 + (tid >> 5);
    const int lane = tid & 31;
    const int b = w >> 10;
    const int i = w & 1023;

    float mu = mu_b[i];
    float sg = sig_b[i];
    #pragma unroll
    for (int s = 0; s < MS_SPLIT; ++s) {
        mu += g_part[MU_OFF  + (s * BATCH + b) * NTOK + i];
        sg += g_part[SIG_OFF + (s * BATCH + b) * NTOK + i];
    }
    mu = tanhf(mu);
    const float coef = -0.5f / (sg * sg + 1e-8f);

    const float4* K4 = reinterpret_cast<const float4*>(Kp) + (size_t)w * (DDIM / 4);
    const float4* V4 = reinterpret_cast<const float4*>(Vp) + (size_t)w * (DDIM / 4);

    float acc = 0.f;
    #pragma unroll
    for (int it = 0; it < 8; ++it) {
        const float4 k4 = __ldcs(&K4[it * 32 + lane]);
        const float4 v4 = __ldcs(&V4[it * 32 + lane]);
        float d;
        d = k4.x - mu; acc += __expf(coef * d * d) * v4.x;
        d = k4.y - mu; acc += __expf(coef * d * d) * v4.y;
        d = k4.z - mu; acc += __expf(coef * d * d) * v4.z;
        d = k4.w - mu; acc += __expf(coef * d * d) * v4.w;
    }
    #pragma unroll
    for (int o = 16; o; o >>= 1) acc += __shfl_xor_sync(0xffffffffu, acc, o);

    __shared__ float shv[8];
    if (lane == 0) {
        const float v = acc + Qp[w];
        g_x[w] = v;
        shv[tid >> 5] = v;
    }
    __syncthreads();
    if (tid < 32) {
        float v = (lane < 8) ? shv[lane] : 0.f;
        float s = v, ss = v * v;
        #pragma unroll
        for (int o = 4; o; o >>= 1) {
            s  += __shfl_xor_sync(0xffffffffu, s,  o);
            ss += __shfl_xor_sync(0xffffffffu, ss, o);
        }
        if (lane == 0) {
            atomicAdd(&g_xraw[2 * b],     s);
            atomicAdd(&g_xraw[2 * b + 1], ss);
        }
    }
}

// =====================================================================
// final combine: out = x + b2 + sum of F2_SPLIT partials   (32 x 1024)
// =====================================================================
__global__ void final_kernel(const float* __restrict__ b2,
                             float* __restrict__ out)
{
    const int t  = blockIdx.x * blockDim.x + threadIdx.x;   // 0..8191 float4s
    const int m  = t >> 8;
    const int j4 = t & 255;
    float4 s = reinterpret_cast<const float4*>(g_x)[t];
    const float4 bb = reinterpret_cast<const float4*>(b2)[j4];
    s.x += bb.x; s.y += bb.y; s.z += bb.z; s.w += bb.w;
    #pragma unroll
    for (int sp = 0; sp < F2_SPLIT; ++sp) {
        const float4 p = *reinterpret_cast<const float4*>(
            g_part + W2_OFF + (size_t)(sp * BATCH + m) * NTOK + j4 * 4);
        s.x += p.x; s.y += p.y; s.z += p.z; s.w += p.w;
    }
    reinterpret_cast<float4*>(out)[t] = s;
}

// =====================================================================
extern "C" void kernel_launch(void* const* d_in, const int* in_sizes, int n_in,
                              void* d_out, int out_size)
{
    const float* Q       = (const float*)d_in[0];
    const float* Kt      = (const float*)d_in[1];
    const float* Vt      = (const float*)d_in[2];
    const float* mu_w    = (const float*)d_in[3];
    const float* mu_b    = (const float*)d_in[4];
    const float* sigma_w = (const float*)d_in[5];
    const float* sigma_b = (const float*)d_in[6];
    const float* ffn_w1  = (const float*)d_in[7];
    const float* ffn_b1  = (const float*)d_in[8];
    const float* ffn_w2  = (const float*)d_in[9];
    const float* ffn_b2  = (const float*)d_in[10];
    const float* ln_ff_g = (const float*)d_in[11];
    const float* ln_ff_b = (const float*)d_in[12];
    const float* ln_q_g  = (const float*)d_in[13];
    const float* ln_q_b  = (const float*)d_in[14];
    float* out = (float*)d_out;

    // 1. Q row stats + zero x-stat accumulators
    stats_kernel<<<1, 1024>>>(Q);

    // 2. mu & sigma partial GEMMs on LN(Q), split-K 16, z selects matrix
    gemm_kernel<0><<<dim3(NTOK / 128, MS_SPLIT, 2), 256>>>(
        mu_w, sigma_w, NTOK, NTOK, NTOK / MS_SPLIT,
        MU_OFF, SIG_OFF - MU_OFF, Q, ln_q_g, ln_q_b, nullptr);

    // 3. Gaussian stream + mu/sigma combine + x-stat atomics
    gauss_kernel<<<(BATCH * NTOK) / 8, 256>>>(Kt, Vt, Q, mu_b, sigma_b);

    // 4. FFN GEMM 1 on LN(g_x) (stats from g_xraw), split-K 8
    gemm_kernel<1><<<dim3(MFF / 128, F1_SPLIT, 1), 256>>>(
        ffn_w1, ffn_w1, NTOK, MFF, NTOK / F1_SPLIT,
        W1_OFF, 0, nullptr, ln_ff_g, ln_ff_b, nullptr);

    // 5. FFN GEMM 2 on silu(partials + b1), split-K 32
    gemm_kernel<2><<<dim3(NTOK / 128, F2_SPLIT, 1), 256>>>(
        ffn_w2, ffn_w2, MFF, NTOK, MFF / F2_SPLIT,
        W2_OFF, 0, nullptr, nullptr, nullptr, ffn_b1);

    // 6. out = x + b2 + sum of FFN2 partials
    final_kernel<<<BATCH, 256>>>(ffn_b2, out);
}

// round 5
// speedup vs baseline: 1.2337x; 1.2337x over previous
#include <cuda_runtime.h>
#include <cstdint>

// ---------------- problem constants ----------------
#define BATCH   32
#define NTOK    1024
#define DDIM    1024
#define MFF     4096
#define LN_EPS  1e-5f
#define GKC     16

#define MS_SPLIT 16
#define F1_SPLIT 16
#define F2_SPLIT 32

// ---------------- scratch ----------------
__device__ float g_x    [BATCH * NTOK];
__device__ float g_qstat[64];                 // (mean, rstd) per Q row
__device__ float g_xraw [64];                 // (sum, sumsq) per x row (atomics)
__device__ float g_part [3145728];            // split-K partials (12 MB)

#define MU_OFF  0                             // 16*32*1024 = 524288
#define SIG_OFF 524288
#define W1_OFF  0                             // 16*32*4096 = 2097152 (reuse)
#define W2_OFF  2097152                       // 32*32*1024 = 1048576

// =====================================================================
// Q row stats (mean, rstd) + zero the x-stat accumulators. 1 block.
// =====================================================================
__global__ void stats_kernel(const float* __restrict__ Q)
{
    const int tid = threadIdx.x;
    if (tid < 64) g_xraw[tid] = 0.f;
    const int r = tid >> 5, lane = tid & 31;
    const float4* p = reinterpret_cast<const float4*>(Q + r * NTOK);
    float s = 0.f, ss = 0.f;
    #pragma unroll
    for (int i = 0; i < 8; ++i) {
        float4 v = p[lane + 32 * i];
        s  += v.x + v.y + v.z + v.w;
        ss += v.x*v.x + v.y*v.y + v.z*v.z + v.w*v.w;
    }
    #pragma unroll
    for (int o = 16; o; o >>= 1) {
        s  += __shfl_xor_sync(0xffffffffu, s,  o);
        ss += __shfl_xor_sync(0xffffffffu, ss, o);
    }
    if (lane == 0) {
        const float mean = s * (1.0f / NTOK);
        const float var  = ss * (1.0f / NTOK) - mean * mean;
        g_qstat[2 * r]     = mean;
        g_qstat[2 * r + 1] = rsqrtf(var + LN_EPS);
    }
}

// =====================================================================
// Split-K GEMM. Block tile 32(M) x 256(N), K-chunk 16, double-buffered.
// Thread tile 8m x 4n -> 16 fma.f32x2 per kk against 5 LDS (1x LDS.128 W,
// 4x broadcast LDS.128 of duplicated A). FFMA2 pairs run over n so W is
// stored plain; only the 32-row A panel is duplicated.
// A rows padded to 68 floats (272 B) so every 16B vector load is aligned.
// AMODE 0: A = LN(Q)  (g_qstat)   1: A = LN(g_x) (g_xraw)
// AMODE 2: A = silu(sum of F1_SPLIT partials + b1)
// gridDim = (N/256, nsplit, nz); z selects W0/W1 (mu/sigma fusion).
// =====================================================================
template<int AMODE>
__global__ __launch_bounds__(256, 2)
void gemm_kernel(const float* __restrict__ W0, const float* __restrict__ W1,
                 int ldw, int N, int kPerSplit, int partOff, int partStrideZ,
                 const float* __restrict__ Ain,
                 const float* __restrict__ lng, const float* __restrict__ lnb,
                 const float* __restrict__ b1)
{
    __shared__ __align__(16) float a_s[2][GKC][68];    //  8.7 KB (dup A, 272B rows)
    __shared__ __align__(16) float w_s[2][GKC][264];   // 33.8 KB (plain W, 1056B rows)

    const int tid = threadIdx.x;
    const float* __restrict__ W = (blockIdx.z == 0) ? W0 : W1;
    float* __restrict__ P = g_part + partOff + (size_t)blockIdx.z * partStrideZ;

    const int j0    = blockIdx.x * 256;
    const int split = blockIdx.y;
    const int kOff  = split * kPerSplit;
    const int T     = kPerSplit / GKC;

    // W loader: one n-row per thread, full 16-float chunk
    const float* Wrow = W + (size_t)(j0 + tid) * ldw + kOff;
    // A loader: threads 0..127, float4 each
    const int ra = tid >> 2, c4 = (tid & 3) * 4;
    // compute mapping
    const int tx = tid & 63, ty = tid >> 6;

    float mean = 0.f, rs = 0.f;
    if (AMODE == 0 && tid < 128) {
        mean = g_qstat[2 * ra];  rs = g_qstat[2 * ra + 1];
    }
    if (AMODE == 1 && tid < 128) {
        const float s  = g_xraw[2 * ra];
        const float ss = g_xraw[2 * ra + 1];
        mean = s * (1.0f / NTOK);
        rs   = rsqrtf(ss * (1.0f / NTOK) - mean * mean + LN_EPS);
    }
    const float* Arow = (AMODE == 1) ? (g_x + ra * NTOK) : (Ain + ra * NTOK);

    float4 wv[4];
    float  av[4];

    auto loadG = [&](int t) {
        const int kb = t * GKC;
        #pragma unroll
        for (int j = 0; j < 4; ++j)
            wv[j] = *reinterpret_cast<const float4*>(Wrow + kb + 4 * j);
        if (tid < 128) {
            const int kc = kOff + kb + c4;
            if (AMODE < 2) {
                const float4 fa = *reinterpret_cast<const float4*>(Arow + kc);
                const float4 fg = *reinterpret_cast<const float4*>(lng + kc);
                const float4 fb = *reinterpret_cast<const float4*>(lnb + kc);
                av[0] = (fa.x - mean) * rs * fg.x + fb.x;
                av[1] = (fa.y - mean) * rs * fg.y + fb.y;
                av[2] = (fa.z - mean) * rs * fg.z + fb.z;
                av[3] = (fa.w - mean) * rs * fg.w + fb.w;
            } else {
                float4 v = *reinterpret_cast<const float4*>(b1 + kc);
                #pragma unroll
                for (int s = 0; s < F1_SPLIT; ++s) {
                    const float4 p = *reinterpret_cast<const float4*>(
                        g_part + W1_OFF + (size_t)(s * BATCH + ra) * MFF + kc);
                    v.x += p.x; v.y += p.y; v.z += p.z; v.w += p.w;
                }
                av[0] = v.x / (1.0f + __expf(-v.x));
                av[1] = v.y / (1.0f + __expf(-v.y));
                av[2] = v.z / (1.0f + __expf(-v.z));
                av[3] = v.w / (1.0f + __expf(-v.w));
            }
        }
    };

    auto storeS = [&](int buf) {
        w_s[buf][ 0][tid] = wv[0].x;  w_s[buf][ 1][tid] = wv[0].y;
        w_s[buf][ 2][tid] = wv[0].z;  w_s[buf][ 3][tid] = wv[0].w;
        w_s[buf][ 4][tid] = wv[1].x;  w_s[buf][ 5][tid] = wv[1].y;
        w_s[buf][ 6][tid] = wv[1].z;  w_s[buf][ 7][tid] = wv[1].w;
        w_s[buf][ 8][tid] = wv[2].x;  w_s[buf][ 9][tid] = wv[2].y;
        w_s[buf][10][tid] = wv[2].z;  w_s[buf][11][tid] = wv[2].w;
        w_s[buf][12][tid] = wv[3].x;  w_s[buf][13][tid] = wv[3].y;
        w_s[buf][14][tid] = wv[3].z;  w_s[buf][15][tid] = wv[3].w;
        if (tid < 128) {
            #pragma unroll
            for (int j = 0; j < 4; ++j)
                *reinterpret_cast<float2*>(&a_s[buf][c4 + j][2 * ra]) =
                    make_float2(av[j], av[j]);
        }
    };

    loadG(0);
    storeS(0);
    __syncthreads();

    unsigned long long acc[8][2];
    #pragma unroll
    for (int r = 0; r < 8; ++r) { acc[r][0] = 0ull; acc[r][1] = 0ull; }

    for (int t = 0; t < T; ++t) {
        const int cur = t & 1;
        if (t + 1 < T) loadG(t + 1);
        #pragma unroll
        for (int kk = 0; kk < GKC; ++kk) {
            const ulonglong2 w =
                *reinterpret_cast<const ulonglong2*>(&w_s[cur][kk][4 * tx]);
            #pragma unroll
            for (int j = 0; j < 4; ++j) {
                const ulonglong2 a =
                    *reinterpret_cast<const ulonglong2*>(&a_s[cur][kk][16 * ty + 4 * j]);
                asm("fma.rn.f32x2 %0, %1, %2, %0;" : "+l"(acc[2*j  ][0]) : "l"(a.x), "l"(w.x));
                asm("fma.rn.f32x2 %0, %1, %2, %0;" : "+l"(acc[2*j  ][1]) : "l"(a.x), "l"(w.y));
                asm("fma.rn.f32x2 %0, %1, %2, %0;" : "+l"(acc[2*j+1][0]) : "l"(a.y), "l"(w.x));
                asm("fma.rn.f32x2 %0, %1, %2, %0;" : "+l"(acc[2*j+1][1]) : "l"(a.y), "l"(w.y));
            }
        }
        if (t + 1 < T) {
            storeS((t + 1) & 1);
            __syncthreads();
        }
    }

    // epilogue: rows 8ty..8ty+7, cols j0+4tx..j0+4tx+3
    #pragma unroll
    for (int r = 0; r < 8; ++r) {
        float f0, f1, f2, f3;
        asm("mov.b64 {%0, %1}, %2;" : "=f"(f0), "=f"(f1) : "l"(acc[r][0]));
        asm("mov.b64 {%0, %1}, %2;" : "=f"(f2), "=f"(f3) : "l"(acc[r][1]));
        float* dst = P + (size_t)(split * BATCH + 8 * ty + r) * N + j0 + 4 * tx;
        *reinterpret_cast<float4*>(dst) = make_float4(f0, f1, f2, f3);
    }
}

// =====================================================================
// Gaussian pseudo-attention: one warp per (b,i), streams K/V (256 MB).
// Folds mu/sigma split-K combine; accumulates LN(x) stats via atomics.
// =====================================================================
__global__ __launch_bounds__(256)
void gauss_kernel(const float* __restrict__ Kp,
                  const float* __restrict__ Vp,
                  const float* __restrict__ Qp,
                  const float* __restrict__ mu_b,
                  const float* __restrict__ sig_b)
{
    const int tid  = threadIdx.x;
    const int w    = blockIdx.x * 8 + (tid >> 5);
    const int lane = tid & 31;
    const int b = w >> 10;
    const int i = w & 1023;

    float mu = mu_b[i];
    float sg = sig_b[i];
    #pragma unroll
    for (int s = 0; s < MS_SPLIT; ++s) {
        mu += g_part[MU_OFF  + (s * BATCH + b) * NTOK + i];
        sg += g_part[SIG_OFF + (s * BATCH + b) * NTOK + i];
    }
    mu = tanhf(mu);
    const float coef = -0.5f / (sg * sg + 1e-8f);

    const float4* K4 = reinterpret_cast<const float4*>(Kp) + (size_t)w * (DDIM / 4);
    const float4* V4 = reinterpret_cast<const float4*>(Vp) + (size_t)w * (DDIM / 4);

    float acc = 0.f;
    #pragma unroll
    for (int it = 0; it < 8; ++it) {
        const float4 k4 = __ldcs(&K4[it * 32 + lane]);
        const float4 v4 = __ldcs(&V4[it * 32 + lane]);
        float d;
        d = k4.x - mu; acc += __expf(coef * d * d) * v4.x;
        d = k4.y - mu; acc += __expf(coef * d * d) * v4.y;
        d = k4.z - mu; acc += __expf(coef * d * d) * v4.z;
        d = k4.w - mu; acc += __expf(coef * d * d) * v4.w;
    }
    #pragma unroll
    for (int o = 16; o; o >>= 1) acc += __shfl_xor_sync(0xffffffffu, acc, o);

    __shared__ float shv[8];
    if (lane == 0) {
        const float v = acc + Qp[w];
        g_x[w] = v;
        shv[tid >> 5] = v;
    }
    __syncthreads();
    if (tid < 32) {
        float v = (lane < 8) ? shv[lane] : 0.f;
        float s = v, ss = v * v;
        #pragma unroll
        for (int o = 4; o; o >>= 1) {
            s  += __shfl_xor_sync(0xffffffffu, s,  o);
            ss += __shfl_xor_sync(0xffffffffu, ss, o);
        }
        if (lane == 0) {
            atomicAdd(&g_xraw[2 * b],     s);
            atomicAdd(&g_xraw[2 * b + 1], ss);
        }
    }
}

// =====================================================================
// final combine: out = x + b2 + sum of F2_SPLIT partials   (32 x 1024)
// =====================================================================
__global__ void final_kernel(const float* __restrict__ b2,
                             float* __restrict__ out)
{
    const int t  = blockIdx.x * blockDim.x + threadIdx.x;   // 0..8191 float4s
    const int m  = t >> 8;
    const int j4 = t & 255;
    float4 s = reinterpret_cast<const float4*>(g_x)[t];
    const float4 bb = reinterpret_cast<const float4*>(b2)[j4];
    s.x += bb.x; s.y += bb.y; s.z += bb.z; s.w += bb.w;
    #pragma unroll
    for (int sp = 0; sp < F2_SPLIT; ++sp) {
        const float4 p = *reinterpret_cast<const float4*>(
            g_part + W2_OFF + (size_t)(sp * BATCH + m) * NTOK + j4 * 4);
        s.x += p.x; s.y += p.y; s.z += p.z; s.w += p.w;
    }
    reinterpret_cast<float4*>(out)[t] = s;
}

// =====================================================================
extern "C" void kernel_launch(void* const* d_in, const int* in_sizes, int n_in,
                              void* d_out, int out_size)
{
    const float* Q       = (const float*)d_in[0];
    const float* Kt      = (const float*)d_in[1];
    const float* Vt      = (const float*)d_in[2];
    const float* mu_w    = (const float*)d_in[3];
    const float* mu_b    = (const float*)d_in[4];
    const float* sigma_w = (const float*)d_in[5];
    const float* sigma_b = (const float*)d_in[6];
    const float* ffn_w1  = (const float*)d_in[7];
    const float* ffn_b1  = (const float*)d_in[8];
    const float* ffn_w2  = (const float*)d_in[9];
    const float* ffn_b2  = (const float*)d_in[10];
    const float* ln_ff_g = (const float*)d_in[11];
    const float* ln_ff_b = (const float*)d_in[12];
    const float* ln_q_g  = (const float*)d_in[13];
    const float* ln_q_b  = (const float*)d_in[14];
    float* out = (float*)d_out;

    // 1. Q row stats + zero x-stat accumulators
    stats_kernel<<<1, 1024>>>(Q);

    // 2. mu & sigma partial GEMMs on LN(Q), split-K 16, z selects matrix
    gemm_kernel<0><<<dim3(NTOK / 256, MS_SPLIT, 2), 256>>>(
        mu_w, sigma_w, NTOK, NTOK, NTOK / MS_SPLIT,
        MU_OFF, SIG_OFF - MU_OFF, Q, ln_q_g, ln_q_b, nullptr);

    // 3. Gaussian stream + mu/sigma combine + x-stat atomics
    gauss_kernel<<<(BATCH * NTOK) / 8, 256>>>(Kt, Vt, Q, mu_b, sigma_b);

    // 4. FFN GEMM 1 on LN(g_x), split-K 16
    gemm_kernel<1><<<dim3(MFF / 256, F1_SPLIT, 1), 256>>>(
        ffn_w1, ffn_w1, NTOK, MFF, NTOK / F1_SPLIT,
        W1_OFF, 0, nullptr, ln_ff_g, ln_ff_b, nullptr);

    // 5. FFN GEMM 2 on silu(partials + b1), split-K 32
    gemm_kernel<2><<<dim3(NTOK / 256, F2_SPLIT, 1), 256>>>(
        ffn_w2, ffn_w2, MFF, NTOK, MFF / F2_SPLIT,
        W2_OFF, 0, nullptr, nullptr, nullptr, ffn_b1);

    // 6. out = x + b2 + sum of FFN2 partials
    final_kernel<<<BATCH, 256>>>(ffn_b2, out);
}

// round 6
// speedup vs baseline: 1.2703x; 1.0296x over previous
#include <cuda_runtime.h>
#include <cstdint>

// ---------------- problem constants ----------------
#define BATCH   32
#define NTOK    1024
#define DDIM    1024
#define MFF     4096
#define LN_EPS  1e-5f

#define MS_SPLIT 16
#define F1_SPLIT 8
#define F2_SPLIT 64

// ---------------- scratch ----------------
__device__ float g_x    [BATCH * NTOK];
__device__ float g_qstat[64];                 // (mean, rstd) per Q row
__device__ float g_xraw [64];                 // (sum, sumsq) per x row (atomics)
__device__ float g_part [3145728];            // split-K partials (12 MB)

#define MU_OFF  0                             // 16*32*1024 = 524288
#define SIG_OFF 524288
#define W1_OFF  0                             // 8*32*4096 = 1048576 (reused)
#define W2_OFF  1048576                       // 64*32*1024 = 2097152

// dynamic smem sizes: A panel [NCHUNK*64][68] + W panel [64][264]
#define GEMM_SMEM_1 ((64 * 68 + 64 * 264) * 4)     // 84992 B
#define GEMM_SMEM_2 ((128 * 68 + 64 * 264) * 4)    // 102400 B

// =====================================================================
// Q row stats (mean, rstd) + zero the x-stat accumulators. 1 block.
// =====================================================================
__global__ void stats_kernel(const float* __restrict__ Q)
{
    const int tid = threadIdx.x;
    if (tid < 64) g_xraw[tid] = 0.f;
    const int r = tid >> 5, lane = tid & 31;
    const float4* p = reinterpret_cast<const float4*>(Q + r * NTOK);
    float s = 0.f, ss = 0.f;
    #pragma unroll
    for (int i = 0; i < 8; ++i) {
        float4 v = p[lane + 32 * i];
        s  += v.x + v.y + v.z + v.w;
        ss += v.x*v.x + v.y*v.y + v.z*v.z + v.w*v.w;
    }
    #pragma unroll
    for (int o = 16; o; o >>= 1) {
        s  += __shfl_xor_sync(0xffffffffu, s,  o);
        ss += __shfl_xor_sync(0xffffffffu, ss, o);
    }
    if (lane == 0) {
        const float mean = s * (1.0f / NTOK);
        const float var  = ss * (1.0f / NTOK) - mean * mean;
        g_qstat[2 * r]     = mean;
        g_qstat[2 * r + 1] = rsqrtf(var + LN_EPS);
    }
}

// =====================================================================
// Split-K GEMM. Block tile 32(M) x 256(N); K strip = NCHUNK*64 per block.
// Per 64-k chunk: each thread prefetches its whole W row strip with 16
// back-to-back LDG.128 (MLP=16), dumps to a whole-strip smem panel, then
// computes 64 kk with NO syncs: 1 LDS.128 (W) + 4 broadcast LDS.128
// (dup A) + 16 fma.f32x2 per kk. A panel (LN / silu applied) built once.
// AMODE 0: A = LN(Q) (g_qstat)  1: A = LN(g_x) (g_xraw)
// AMODE 2: A = silu(sum of F1_SPLIT partials + b1)
// gridDim = (N/256, nsplit, nz); z selects W0/W1 (mu/sigma fusion).
// =====================================================================
template<int AMODE, int NCHUNK>
__global__ __launch_bounds__(256, 2)
void gemm_kernel(const float* __restrict__ W0, const float* __restrict__ W1,
                 int ldw, int N, int partOff, int partStrideZ,
                 const float* __restrict__ Ain,
                 const float* __restrict__ lng, const float* __restrict__ lnb,
                 const float* __restrict__ b1)
{
    extern __shared__ __align__(16) float smem[];
    float* a_s = smem;                           // [NCHUNK*64][68] dup A
    float* w_s = smem + NCHUNK * 64 * 68;        // [64][264] plain W

    const int tid = threadIdx.x;
    const float* __restrict__ W = (blockIdx.z == 0) ? W0 : W1;
    float* __restrict__ P = g_part + partOff + (size_t)blockIdx.z * partStrideZ;

    const int j0    = blockIdx.x * 256;
    const int split = blockIdx.y;
    const int kOff  = split * (NCHUNK * 64);

    const float* Wrow = W + (size_t)(j0 + tid) * ldw + kOff;

    // ---- prefetch W chunk 0: 16 back-to-back LDG.128 ----
    float4 wreg[16];
    #pragma unroll
    for (int j = 0; j < 16; ++j)
        wreg[j] = *reinterpret_cast<const float4*>(Wrow + 4 * j);

    // ---- build A panel (all chunks) ----
    const int ra = tid >> 3, ca = tid & 7;
    float mean = 0.f, rs = 0.f;
    if (AMODE == 0) { mean = g_qstat[2 * ra]; rs = g_qstat[2 * ra + 1]; }
    if (AMODE == 1) {
        const float s  = g_xraw[2 * ra];
        const float ss = g_xraw[2 * ra + 1];
        mean = s * (1.0f / NTOK);
        rs   = rsqrtf(ss * (1.0f / NTOK) - mean * mean + LN_EPS);
    }
    const float* Arow = (AMODE == 1) ? (g_x + ra * NTOK)
                      : (AMODE == 0) ? (Ain + ra * NTOK) : nullptr;

    #pragma unroll
    for (int c = 0; c < NCHUNK; ++c) {
        #pragma unroll
        for (int h = 0; h < 2; ++h) {
            const int klocal = c * 64 + ca * 8 + h * 4;
            const int kc     = kOff + klocal;
            float av[4];
            if (AMODE < 2) {
                const float4 fa = *reinterpret_cast<const float4*>(Arow + kc);
                const float4 fg = *reinterpret_cast<const float4*>(lng + kc);
                const float4 fb = *reinterpret_cast<const float4*>(lnb + kc);
                av[0] = (fa.x - mean) * rs * fg.x + fb.x;
                av[1] = (fa.y - mean) * rs * fg.y + fb.y;
                av[2] = (fa.z - mean) * rs * fg.z + fb.z;
                av[3] = (fa.w - mean) * rs * fg.w + fb.w;
            } else {
                float4 v = *reinterpret_cast<const float4*>(b1 + kc);
                #pragma unroll
                for (int s = 0; s < F1_SPLIT; ++s) {
                    const float4 p = *reinterpret_cast<const float4*>(
                        g_part + W1_OFF + (size_t)(s * BATCH + ra) * MFF + kc);
                    v.x += p.x; v.y += p.y; v.z += p.z; v.w += p.w;
                }
                av[0] = v.x / (1.0f + __expf(-v.x));
                av[1] = v.y / (1.0f + __expf(-v.y));
                av[2] = v.z / (1.0f + __expf(-v.z));
                av[3] = v.w / (1.0f + __expf(-v.w));
            }
            #pragma unroll
            for (int j = 0; j < 4; ++j)
                *reinterpret_cast<float2*>(&a_s[(klocal + j) * 68 + 2 * ra]) =
                    make_float2(av[j], av[j]);
        }
    }

    // ---- dump W chunk 0 to smem ----
    #pragma unroll
    for (int j = 0; j < 16; ++j) {
        w_s[(4 * j + 0) * 264 + tid] = wreg[j].x;
        w_s[(4 * j + 1) * 264 + tid] = wreg[j].y;
        w_s[(4 * j + 2) * 264 + tid] = wreg[j].z;
        w_s[(4 * j + 3) * 264 + tid] = wreg[j].w;
    }
    __syncthreads();

    // ---- main loop ----
    const int tx = tid & 63, ty = tid >> 6;
    const float* wp = w_s + 4 * tx;

    unsigned long long acc[8][2];
    #pragma unroll
    for (int r = 0; r < 8; ++r) { acc[r][0] = 0ull; acc[r][1] = 0ull; }

    #pragma unroll
    for (int c = 0; c < NCHUNK; ++c) {
        if (c + 1 < NCHUNK) {            // prefetch next chunk during compute
            #pragma unroll
            for (int j = 0; j < 16; ++j)
                wreg[j] = *reinterpret_cast<const float4*>(Wrow + 64 + 4 * j);
        }
        const float* ap = a_s + (c * 64) * 68 + 16 * ty;
        #pragma unroll 16
        for (int kk = 0; kk < 64; ++kk) {
            const ulonglong2 w =
                *reinterpret_cast<const ulonglong2*>(wp + kk * 264);
            #pragma unroll
            for (int j = 0; j < 4; ++j) {
                const ulonglong2 a =
                    *reinterpret_cast<const ulonglong2*>(ap + kk * 68 + 4 * j);
                asm("fma.rn.f32x2 %0, %1, %2, %0;" : "+l"(acc[2*j  ][0]) : "l"(a.x), "l"(w.x));
                asm("fma.rn.f32x2 %0, %1, %2, %0;" : "+l"(acc[2*j  ][1]) : "l"(a.x), "l"(w.y));
                asm("fma.rn.f32x2 %0, %1, %2, %0;" : "+l"(acc[2*j+1][0]) : "l"(a.y), "l"(w.x));
                asm("fma.rn.f32x2 %0, %1, %2, %0;" : "+l"(acc[2*j+1][1]) : "l"(a.y), "l"(w.y));
            }
        }
        if (c + 1 < NCHUNK) {
            __syncthreads();
            #pragma unroll
            for (int j = 0; j < 16; ++j) {
                w_s[(4 * j + 0) * 264 + tid] = wreg[j].x;
                w_s[(4 * j + 1) * 264 + tid] = wreg[j].y;
                w_s[(4 * j + 2) * 264 + tid] = wreg[j].z;
                w_s[(4 * j + 3) * 264 + tid] = wreg[j].w;
            }
            __syncthreads();
        }
    }

    // ---- epilogue: rows 8ty..8ty+7, cols j0+4tx..j0+4tx+3 ----
    #pragma unroll
    for (int r = 0; r < 8; ++r) {
        float f0, f1, f2, f3;
        asm("mov.b64 {%0, %1}, %2;" : "=f"(f0), "=f"(f1) : "l"(acc[r][0]));
        asm("mov.b64 {%0, %1}, %2;" : "=f"(f2), "=f"(f3) : "l"(acc[r][1]));
        float* dst = P + (size_t)(split * BATCH + 8 * ty + r) * N + j0 + 4 * tx;
        *reinterpret_cast<float4*>(dst) = make_float4(f0, f1, f2, f3);
    }
}

// =====================================================================
// Gaussian pseudo-attention: one warp per (b,i), streams K/V (256 MB)
// with all 16 row loads batched up front (MLP=16). Folds mu/sigma
// split-K combine; accumulates LN(x) stats via atomics.
// =====================================================================
__global__ __launch_bounds__(256)
void gauss_kernel(const float* __restrict__ Kp,
                  const float* __restrict__ Vp,
                  const float* __restrict__ Qp,
                  const float* __restrict__ mu_b,
                  const float* __restrict__ sig_b)
{
    const int tid  = threadIdx.x;
    const int w    = blockIdx.x * 8 + (tid >> 5);
    const int lane = tid & 31;
    const int b = w >> 10;
    const int i = w & 1023;

    float mu = mu_b[i];
    float sg = sig_b[i];
    #pragma unroll
    for (int s = 0; s < MS_SPLIT; ++s) {
        mu += g_part[MU_OFF  + (s * BATCH + b) * NTOK + i];
        sg += g_part[SIG_OFF + (s * BATCH + b) * NTOK + i];
    }
    mu = tanhf(mu);
    const float coef = -0.5f / (sg * sg + 1e-8f);

    const float4* K4 = reinterpret_cast<const float4*>(Kp) + (size_t)w * (DDIM / 4);
    const float4* V4 = reinterpret_cast<const float4*>(Vp) + (size_t)w * (DDIM / 4);

    float4 kr[8], vr[8];
    #pragma unroll
    for (int it = 0; it < 8; ++it) kr[it] = __ldcs(&K4[it * 32 + lane]);
    #pragma unroll
    for (int it = 0; it < 8; ++it) vr[it] = __ldcs(&V4[it * 32 + lane]);

    float acc = 0.f;
    #pragma unroll
    for (int it = 0; it < 8; ++it) {
        float d;
        d = kr[it].x - mu; acc += __expf(coef * d * d) * vr[it].x;
        d = kr[it].y - mu; acc += __expf(coef * d * d) * vr[it].y;
        d = kr[it].z - mu; acc += __expf(coef * d * d) * vr[it].z;
        d = kr[it].w - mu; acc += __expf(coef * d * d) * vr[it].w;
    }
    #pragma unroll
    for (int o = 16; o; o >>= 1) acc += __shfl_xor_sync(0xffffffffu, acc, o);

    __shared__ float shv[8];
    if (lane == 0) {
        const float v = acc + Qp[w];
        g_x[w] = v;
        shv[tid >> 5] = v;
    }
    __syncthreads();
    if (tid < 32) {
        float v = (lane < 8) ? shv[lane] : 0.f;
        float s = v, ss = v * v;
        #pragma unroll
        for (int o = 4; o; o >>= 1) {
            s  += __shfl_xor_sync(0xffffffffu, s,  o);
            ss += __shfl_xor_sync(0xffffffffu, ss, o);
        }
        if (lane == 0) {
            atomicAdd(&g_xraw[2 * b],     s);
            atomicAdd(&g_xraw[2 * b + 1], ss);
        }
    }
}

// =====================================================================
// final combine: out = x + b2 + sum of F2_SPLIT partials   (32 x 1024)
// =====================================================================
__global__ void final_kernel(const float* __restrict__ b2,
                             float* __restrict__ out)
{
    const int t  = blockIdx.x * blockDim.x + threadIdx.x;   // 0..8191 float4s
    const int m  = t >> 8;
    const int j4 = t & 255;
    float4 s = reinterpret_cast<const float4*>(g_x)[t];
    const float4 bb = reinterpret_cast<const float4*>(b2)[j4];
    s.x += bb.x; s.y += bb.y; s.z += bb.z; s.w += bb.w;
    #pragma unroll
    for (int sp = 0; sp < F2_SPLIT; ++sp) {
        const float4 p = *reinterpret_cast<const float4*>(
            g_part + W2_OFF + (size_t)(sp * BATCH + m) * NTOK + j4 * 4);
        s.x += p.x; s.y += p.y; s.z += p.z; s.w += p.w;
    }
    reinterpret_cast<float4*>(out)[t] = s;
}

// =====================================================================
extern "C" void kernel_launch(void* const* d_in, const int* in_sizes, int n_in,
                              void* d_out, int out_size)
{
    const float* Q       = (const float*)d_in[0];
    const float* Kt      = (const float*)d_in[1];
    const float* Vt      = (const float*)d_in[2];
    const float* mu_w    = (const float*)d_in[3];
    const float* mu_b    = (const float*)d_in[4];
    const float* sigma_w = (const float*)d_in[5];
    const float* sigma_b = (const float*)d_in[6];
    const float* ffn_w1  = (const float*)d_in[7];
    const float* ffn_b1  = (const float*)d_in[8];
    const float* ffn_w2  = (const float*)d_in[9];
    const float* ffn_b2  = (const float*)d_in[10];
    const float* ln_ff_g = (const float*)d_in[11];
    const float* ln_ff_b = (const float*)d_in[12];
    const float* ln_q_g  = (const float*)d_in[13];
    const float* ln_q_b  = (const float*)d_in[14];
    float* out = (float*)d_out;

    cudaFuncSetAttribute(gemm_kernel<0, 1>,
                         cudaFuncAttributeMaxDynamicSharedMemorySize, GEMM_SMEM_1);
    cudaFuncSetAttribute(gemm_kernel<1, 2>,
                         cudaFuncAttributeMaxDynamicSharedMemorySize, GEMM_SMEM_2);
    cudaFuncSetAttribute(gemm_kernel<2, 1>,
                         cudaFuncAttributeMaxDynamicSharedMemorySize, GEMM_SMEM_1);

    // 1. Q row stats + zero x-stat accumulators
    stats_kernel<<<1, 1024>>>(Q);

    // 2. mu & sigma partial GEMMs on LN(Q), split-K 16, z selects matrix
    gemm_kernel<0, 1><<<dim3(NTOK / 256, MS_SPLIT, 2), 256, GEMM_SMEM_1>>>(
        mu_w, sigma_w, NTOK, NTOK, MU_OFF, SIG_OFF - MU_OFF,
        Q, ln_q_g, ln_q_b, nullptr);

    // 3. Gaussian stream + mu/sigma combine + x-stat atomics
    gauss_kernel<<<(BATCH * NTOK) / 8, 256>>>(Kt, Vt, Q, mu_b, sigma_b);

    // 4. FFN GEMM 1 on LN(g_x), split-K 8, 2 chunks of 64
    gemm_kernel<1, 2><<<dim3(MFF / 256, F1_SPLIT, 1), 256, GEMM_SMEM_2>>>(
        ffn_w1, ffn_w1, NTOK, MFF, W1_OFF, 0,
        nullptr, ln_ff_g, ln_ff_b, nullptr);

    // 5. FFN GEMM 2 on silu(partials + b1), split-K 64
    gemm_kernel<2, 1><<<dim3(NTOK / 256, F2_SPLIT, 1), 256, GEMM_SMEM_1>>>(
        ffn_w2, ffn_w2, MFF, NTOK, W2_OFF, 0,
        nullptr, nullptr, nullptr, ffn_b1);

    // 6. out = x + b2 + sum of FFN2 partials
    final_kernel<<<64, 128>>>(ffn_b2, out);
}